// round 1
// baseline (speedup 1.0000x reference)
#include <cuda_runtime.h>
#include <math.h>

// Problem constants
#define BB 2
#define TT 2048
#define HIDD 2048
#define NH 16
#define NKV 8
#define HD 128
#define QKVW 4096   // (NH + 2*NKV) * HD
#define KOFF 2048   // NH*HD
#define VOFF 3072   // NH*HD + NKV*HD
#define ATT_SCALE 0.08838834764831845f  // 128^-0.5

// Scratch (allocation-free rule: __device__ globals)
__device__ float g_qkv[(size_t)BB * TT * QKVW];   // 64 MB
__device__ float g_attn[(size_t)BB * TT * HIDD];  // 32 MB

// ---------------------------------------------------------------------------
// SGEMM (NT): C[M,N] = A[M,K] @ B[N,K]^T      (both row-major, K contiguous)
// BM=BN=128, BK=16, 256 threads, 8x8 micro-tile
// ---------------------------------------------------------------------------
__global__ void __launch_bounds__(256) sgemm_nt_kernel(
    const float* __restrict__ A, const float* __restrict__ Bw,
    float* __restrict__ C, int M, int N, int K)
{
    constexpr int BM = 128, BN = 128, BK = 16;
    constexpr int LDA = BM + 4;  // padded to dodge transpose-store conflicts
    __shared__ float As[BK][LDA];
    __shared__ float Bs[BK][LDA];

    const int tid = threadIdx.x;
    const int tr = tid >> 4;       // 0..15
    const int tc = tid & 15;       // 0..15
    const int m0 = blockIdx.y * BM;
    const int n0 = blockIdx.x * BN;

    const float* Ab = A + (size_t)m0 * K;
    const float* Bb = Bw + (size_t)n0 * K;

    float acc[8][8];
#pragma unroll
    for (int i = 0; i < 8; i++)
#pragma unroll
        for (int j = 0; j < 8; j++) acc[i][j] = 0.f;

    for (int k0 = 0; k0 < K; k0 += BK) {
        // Load 128x16 tiles of A and B, store transposed [k][m]
#pragma unroll
        for (int l = 0; l < 2; l++) {
            int idx = tid + l * 256;          // 0..511 float4 slots
            int r   = idx >> 2;               // 0..127 tile row
            int c4  = (idx & 3) << 2;         // 0,4,8,12
            float4 av = *(const float4*)(Ab + (size_t)r * K + k0 + c4);
            As[c4 + 0][r] = av.x; As[c4 + 1][r] = av.y;
            As[c4 + 2][r] = av.z; As[c4 + 3][r] = av.w;
            float4 bv = *(const float4*)(Bb + (size_t)r * K + k0 + c4);
            Bs[c4 + 0][r] = bv.x; Bs[c4 + 1][r] = bv.y;
            Bs[c4 + 2][r] = bv.z; Bs[c4 + 3][r] = bv.w;
        }
        __syncthreads();

#pragma unroll
        for (int kk = 0; kk < BK; kk++) {
            float ra[8], rb[8];
            *(float4*)(ra)     = *(const float4*)&As[kk][tr * 8];
            *(float4*)(ra + 4) = *(const float4*)&As[kk][tr * 8 + 4];
            *(float4*)(rb)     = *(const float4*)&Bs[kk][tc * 8];
            *(float4*)(rb + 4) = *(const float4*)&Bs[kk][tc * 8 + 4];
#pragma unroll
            for (int i = 0; i < 8; i++)
#pragma unroll
                for (int j = 0; j < 8; j++)
                    acc[i][j] += ra[i] * rb[j];
        }
        __syncthreads();
    }

#pragma unroll
    for (int i = 0; i < 8; i++) {
        float* Crow = C + (size_t)(m0 + tr * 8 + i) * N + n0 + tc * 8;
        float4 v0 = make_float4(acc[i][0], acc[i][1], acc[i][2], acc[i][3]);
        float4 v1 = make_float4(acc[i][4], acc[i][5], acc[i][6], acc[i][7]);
        *(float4*)(Crow)     = v0;
        *(float4*)(Crow + 4) = v1;
    }
}

// ---------------------------------------------------------------------------
// RoPE in-place on g_qkv: Q heads [0,NH), K heads [NH, NH+NKV)
// ---------------------------------------------------------------------------
__global__ void rope_kernel(const float* __restrict__ cosT,
                            const float* __restrict__ sinT)
{
    const int bt   = blockIdx.x;           // 0 .. B*T-1
    const int head = blockIdx.y;           // 0 .. NH+NKV-1
    const int d    = threadIdx.x;          // 0 .. 63
    const int t    = bt & (TT - 1);

    size_t base = (size_t)bt * QKVW +
                  (head < NH ? head * HD : KOFF + (head - NH) * HD);
    float c = cosT[t * 64 + d];
    float s = sinT[t * 64 + d];
    float x1 = g_qkv[base + d];
    float x2 = g_qkv[base + d + 64];
    g_qkv[base + d]      = x1 * c - x2 * s;
    g_qkv[base + d + 64] = x1 * s + x2 * c;
}

// ---------------------------------------------------------------------------
// Causal GQA flash attention, fp32.
// Block: one (b, h, 64-row Q tile). 256 threads.
// S micro-tile: thread (tr,tc) owns rows {tr+16i}, cols {tc+16j} (stride-16
// mapping keeps LDS.128 conflict-free with stride-132 padded tiles).
// O: thread owns rows {tr+16i} x cols [tc*8, tc*8+8)  -> 32 regs.
// ---------------------------------------------------------------------------
#define ATT_LDK 132   // 128 + 4 pad
#define ATT_LDS 66    // 64 + 2 pad
#define ATT_SMEM_FLOATS (3 * 64 * ATT_LDK + 64 * ATT_LDS + 128)
#define ATT_SMEM_BYTES  (ATT_SMEM_FLOATS * 4)

__global__ void __launch_bounds__(256) attn_kernel()
{
    extern __shared__ float sm[];
    float* Qs     = sm;
    float* Ks     = Qs + 64 * ATT_LDK;
    float* Vs     = Ks + 64 * ATT_LDK;
    float* Ss     = Vs + 64 * ATT_LDK;
    float* corr_s = Ss + 64 * ATT_LDS;
    float* l_s    = corr_s + 64;

    const int q0 = blockIdx.x * 64;
    const int h  = blockIdx.y;
    const int b  = blockIdx.z;
    const int kh = h >> 1;                 // n_rep = 2
    const int tid = threadIdx.x;
    const int tc = tid & 15;
    const int tr = tid >> 4;

    // Load Q tile [64][128]
    {
        const float* qbase = g_qkv + ((size_t)(b * TT + q0)) * QKVW + h * HD;
        for (int idx = tid; idx < 64 * 32; idx += 256) {
            int r  = idx >> 5;
            int c4 = (idx & 31) << 2;
            *(float4*)&Qs[r * ATT_LDK + c4] =
                *(const float4*)(qbase + (size_t)r * QKVW + c4);
        }
    }

    float m_r = -INFINITY, l_r = 0.f;   // row stats (only tid<64 uses)
    float o[4][8];
#pragma unroll
    for (int i = 0; i < 4; i++)
#pragma unroll
        for (int u = 0; u < 8; u++) o[i][u] = 0.f;

    const int ntiles = (q0 >> 6) + 1;
    for (int jt = 0; jt < ntiles; jt++) {
        const int kb = jt << 6;
        __syncthreads();   // previous phase C done (and Q load on first iter)

        // Load K, V tiles
        {
            const float* kbase = g_qkv + ((size_t)(b * TT + kb)) * QKVW + KOFF + kh * HD;
            const float* vbase = g_qkv + ((size_t)(b * TT + kb)) * QKVW + VOFF + kh * HD;
            for (int idx = tid; idx < 64 * 32; idx += 256) {
                int r  = idx >> 5;
                int c4 = (idx & 31) << 2;
                *(float4*)&Ks[r * ATT_LDK + c4] =
                    *(const float4*)(kbase + (size_t)r * QKVW + c4);
                *(float4*)&Vs[r * ATT_LDK + c4] =
                    *(const float4*)(vbase + (size_t)r * QKVW + c4);
            }
        }
        __syncthreads();

        // Phase A: S = Q @ K^T (4x4 micro-tile)
        float s_acc[4][4];
#pragma unroll
        for (int i = 0; i < 4; i++)
#pragma unroll
            for (int j = 0; j < 4; j++) s_acc[i][j] = 0.f;

        for (int d = 0; d < HD; d += 4) {
            float4 qv[4], kv[4];
#pragma unroll
            for (int i = 0; i < 4; i++)
                qv[i] = *(const float4*)&Qs[(tr + 16 * i) * ATT_LDK + d];
#pragma unroll
            for (int j = 0; j < 4; j++)
                kv[j] = *(const float4*)&Ks[(tc + 16 * j) * ATT_LDK + d];
#pragma unroll
            for (int i = 0; i < 4; i++)
#pragma unroll
                for (int j = 0; j < 4; j++) {
                    s_acc[i][j] += qv[i].x * kv[j].x;
                    s_acc[i][j] += qv[i].y * kv[j].y;
                    s_acc[i][j] += qv[i].z * kv[j].z;
                    s_acc[i][j] += qv[i].w * kv[j].w;
                }
        }

        const bool diag = (kb == q0);
#pragma unroll
        for (int i = 0; i < 4; i++)
#pragma unroll
            for (int j = 0; j < 4; j++) {
                int rr = tr + 16 * i, cc = tc + 16 * j;
                float sv = s_acc[i][j] * ATT_SCALE;
                if (diag && cc > rr) sv = -INFINITY;
                Ss[rr * ATT_LDS + cc] = sv;
            }
        __syncthreads();

        // Phase B: online softmax per row (tid < 64)
        if (tid < 64) {
            float tm = -INFINITY;
#pragma unroll 8
            for (int c = 0; c < 64; c++)
                tm = fmaxf(tm, Ss[tid * ATT_LDS + c]);
            float nm  = fmaxf(m_r, tm);
            float cor = __expf(m_r - nm);
            float sum = 0.f;
#pragma unroll 8
            for (int c = 0; c < 64; c++) {
                float p = __expf(Ss[tid * ATT_LDS + c] - nm);
                Ss[tid * ATT_LDS + c] = p;
                sum += p;
            }
            l_r = l_r * cor + sum;
            m_r = nm;
            corr_s[tid] = cor;
            l_s[tid] = l_r;
        }
        __syncthreads();

        // Rescale O, then O += P @ V
#pragma unroll
        for (int i = 0; i < 4; i++) {
            float cr = corr_s[tr + 16 * i];
#pragma unroll
            for (int u = 0; u < 8; u++) o[i][u] *= cr;
        }

        for (int kk = 0; kk < 64; kk++) {
            float4 v0 = *(const float4*)&Vs[kk * ATT_LDK + tc * 8];
            float4 v1 = *(const float4*)&Vs[kk * ATT_LDK + tc * 8 + 4];
#pragma unroll
            for (int i = 0; i < 4; i++) {
                float p = Ss[(tr + 16 * i) * ATT_LDS + kk];
                o[i][0] += p * v0.x; o[i][1] += p * v0.y;
                o[i][2] += p * v0.z; o[i][3] += p * v0.w;
                o[i][4] += p * v1.x; o[i][5] += p * v1.y;
                o[i][6] += p * v1.z; o[i][7] += p * v1.w;
            }
        }
    }

    // Epilogue: normalize and store to g_attn [B*T][NH*HD]
#pragma unroll
    for (int i = 0; i < 4; i++) {
        int r = tr + 16 * i;
        float inv = 1.f / l_s[r];
        float* obase = g_attn + ((size_t)(b * TT + q0 + r)) * HIDD + h * HD + tc * 8;
        float4 r0 = make_float4(o[i][0] * inv, o[i][1] * inv, o[i][2] * inv, o[i][3] * inv);
        float4 r1 = make_float4(o[i][4] * inv, o[i][5] * inv, o[i][6] * inv, o[i][7] * inv);
        *(float4*)(obase)     = r0;
        *(float4*)(obase + 4) = r1;
    }
}

// ---------------------------------------------------------------------------
extern "C" void kernel_launch(void* const* d_in, const int* in_sizes, int n_in,
                              void* d_out, int out_size)
{
    const float* hidden = (const float*)d_in[0];
    const float* fcos   = (const float*)d_in[1];
    const float* fsin   = (const float*)d_in[2];
    // d_in[3] k_cache, d_in[4] v_cache, d_in[5] mask, d_in[8] indices: analytic
    const float* w_qkv  = (const float*)d_in[6];
    const float* w_o    = (const float*)d_in[7];
    float* out = (float*)d_out;

    float *qkv_ptr, *attn_ptr;
    cudaGetSymbolAddress((void**)&qkv_ptr, g_qkv);
    cudaGetSymbolAddress((void**)&attn_ptr, g_attn);

    cudaFuncSetAttribute(attn_kernel,
                         cudaFuncAttributeMaxDynamicSharedMemorySize,
                         ATT_SMEM_BYTES);

    const int M = BB * TT;  // 4096

    // 1) QKV projection: [4096,2048] @ [4096,2048]^T -> [4096,4096]
    sgemm_nt_kernel<<<dim3(QKVW / 128, M / 128), 256>>>(
        hidden, w_qkv, qkv_ptr, M, QKVW, HIDD);

    // 2) RoPE on Q and K heads (in-place)
    rope_kernel<<<dim3(BB * TT, NH + NKV), 64>>>(fcos, fsin);

    // 3) Causal GQA attention -> g_attn [4096, 2048]
    attn_kernel<<<dim3(TT / 64, NH, BB), 256, ATT_SMEM_BYTES>>>();

    // 4) Output projection: [4096,2048] @ [2048,2048]^T -> d_out
    sgemm_nt_kernel<<<dim3(HIDD / 128, M / 128), 256>>>(
        attn_ptr, w_o, out, M, HIDD, HIDD);
}

// round 3
// speedup vs baseline: 1.3784x; 1.3784x over previous
#include <cuda_runtime.h>
#include <cuda_bf16.h>
#include <math.h>
#include <stdint.h>

// Problem constants
#define BB 2
#define TT 2048
#define HIDD 2048
#define NH 16
#define NKV 8
#define HD 128
#define QKVW 4096   // (NH + 2*NKV) * HD
#define KOFF 2048   // NH*HD
#define VOFF 3072   // NH*HD + NKV*HD
#define ATT_SCALE 0.08838834764831845f  // 128^-0.5

// Scratch (allocation-free rule: __device__ globals)
__device__ float g_qkv[(size_t)BB * TT * QKVW];   // 64 MB
__device__ float g_attn[(size_t)BB * TT * HIDD];  // 32 MB

// ---------------------------------------------------------------------------
// Helpers (arch-stable PTX only: ldmatrix + mma.sync, sm_80+)
// ---------------------------------------------------------------------------
__device__ __forceinline__ uint32_t smem_u32(const void* p) {
    uint32_t a;
    asm("{ .reg .u64 t; cvta.to.shared.u64 t, %1; cvt.u32.u64 %0, t; }"
        : "=r"(a) : "l"(p));
    return a;
}

// pack two f32 -> bf16x2 (lo = x, hi = y), round-to-nearest
__device__ __forceinline__ uint32_t pack_bf2(float x, float y) {
    uint32_t r;
    asm("cvt.rn.bf16x2.f32 %0, %1, %2;" : "=r"(r) : "f"(y), "f"(x));
    return r;
}

#define LDM_X4(r, a)                                                            \
    asm volatile("ldmatrix.sync.aligned.m8n8.x4.shared.b16 {%0,%1,%2,%3}, [%4];"\
        : "=r"((r)[0]), "=r"((r)[1]), "=r"((r)[2]), "=r"((r)[3]) : "r"(a))

__device__ __forceinline__ void mma_bf16(float* d, const uint32_t* a, const uint32_t* b) {
    asm volatile(
        "mma.sync.aligned.m16n8k16.row.col.f32.bf16.bf16.f32 "
        "{%0,%1,%2,%3}, {%4,%5,%6,%7}, {%8,%9}, {%0,%1,%2,%3};"
        : "+f"(d[0]), "+f"(d[1]), "+f"(d[2]), "+f"(d[3])
        : "r"(a[0]), "r"(a[1]), "r"(a[2]), "r"(a[3]), "r"(b[0]), "r"(b[1]));
}

// ---------------------------------------------------------------------------
// Tensor-core NT GEMM: C[M,N] = A[M,K] @ B[N,K]^T, fp32 in/out.
// bf16 2-term split (hi+lo), 3 MMA products, fp32 accumulate.
// CTA tile 128x128, BK=32, 8 warps (4m x 2n -> 32x64 per warp), double buffer.
// SMEM rows padded to 40 bf16 (80B) => conflict-free ldmatrix.
// ---------------------------------------------------------------------------
#define BKC 32
#define LDT 80                      // bytes per smem row (32+8 bf16)
#define TILE_B (128 * LDT)          // 10240 B per 128x32 bf16 tile
#define STG_B  (4 * TILE_B)         // A_hi, A_lo, B_hi, B_lo
#define GEMM_SMEM (2 * STG_B)       // 81920 B

__global__ void __launch_bounds__(256, 1) gemm_bf16s_kernel(
    const float* __restrict__ A, const float* __restrict__ Bw,
    float* __restrict__ C, int M, int N, int K)
{
    extern __shared__ char sm[];
    const uint32_t smb = smem_u32(sm);
    const int tid  = threadIdx.x;
    const int wid  = tid >> 5;
    const int lane = tid & 31;
    const int m0 = blockIdx.y * 128;
    const int n0 = blockIdx.x * 128;
    const int wm = wid & 3;          // 0..3 (m quadrant, 32 rows)
    const int wn = wid >> 2;         // 0..1 (n half, 64 cols)
    const int quad = lane >> 3;
    const int rin  = lane & 7;

    const float* Ab = A + (size_t)m0 * K;
    const float* Bb = Bw + (size_t)n0 * K;
    const int NC = K / BKC;

    float acc[2][8][4];
#pragma unroll
    for (int i = 0; i < 2; i++)
#pragma unroll
        for (int j = 0; j < 8; j++)
#pragma unroll
            for (int u = 0; u < 4; u++) acc[i][j][u] = 0.f;

    float4 ra[4], rb[4];   // prefetch registers

    // ---- LDG chunk c into regs ----
#define GEMM_LDG(c)                                                            \
    do {                                                                       \
        _Pragma("unroll")                                                      \
        for (int i = 0; i < 4; i++) {                                          \
            int f = tid * 4 + i;                                               \
            int r = f >> 3, cc = (f & 7) << 2;                                 \
            ra[i] = *(const float4*)(Ab + (size_t)r * K + (c) * BKC + cc);     \
            rb[i] = *(const float4*)(Bb + (size_t)r * K + (c) * BKC + cc);     \
        }                                                                      \
    } while (0)

    // ---- split + STS regs into stage s ----
#define GEMM_STS(s)                                                            \
    do {                                                                       \
        char* base = sm + (s) * STG_B;                                         \
        _Pragma("unroll")                                                      \
        for (int i = 0; i < 4; i++) {                                          \
            int f = tid * 4 + i;                                               \
            int r = f >> 3, cc = (f & 7) << 2;                                 \
            uint32_t off = (uint32_t)(r * LDT + cc * 2);                       \
            float4 v = ra[i];                                                  \
            uint32_t h0 = pack_bf2(v.x, v.y), h1 = pack_bf2(v.z, v.w);         \
            float l0x = v.x - __uint_as_float(h0 << 16);                       \
            float l0y = v.y - __uint_as_float(h0 & 0xFFFF0000u);               \
            float l1x = v.z - __uint_as_float(h1 << 16);                       \
            float l1y = v.w - __uint_as_float(h1 & 0xFFFF0000u);               \
            *(uint2*)(base + off) = make_uint2(h0, h1);                        \
            *(uint2*)(base + TILE_B + off) =                                   \
                make_uint2(pack_bf2(l0x, l0y), pack_bf2(l1x, l1y));            \
            v = rb[i];                                                         \
            h0 = pack_bf2(v.x, v.y); h1 = pack_bf2(v.z, v.w);                  \
            l0x = v.x - __uint_as_float(h0 << 16);                             \
            l0y = v.y - __uint_as_float(h0 & 0xFFFF0000u);                     \
            l1x = v.z - __uint_as_float(h1 << 16);                             \
            l1y = v.w - __uint_as_float(h1 & 0xFFFF0000u);                     \
            *(uint2*)(base + 2 * TILE_B + off) = make_uint2(h0, h1);           \
            *(uint2*)(base + 3 * TILE_B + off) =                               \
                make_uint2(pack_bf2(l0x, l0y), pack_bf2(l1x, l1y));            \
        }                                                                      \
    } while (0)

    // prologue
    GEMM_LDG(0);
    GEMM_STS(0);
    __syncthreads();
    if (NC > 1) GEMM_LDG(1);

    for (int c = 0; c < NC; c++) {
        const uint32_t aBase = smb + (c & 1) * STG_B;
        const uint32_t bBase = aBase + 2 * TILE_B;

#pragma unroll
        for (int ks = 0; ks < 2; ks++) {
            const int k0 = ks * 16;
            uint32_t afh[2][4], afl[2][4], bfh[4][4], bfl[4][4];
#pragma unroll
            for (int mt = 0; mt < 2; mt++) {
                int row = wm * 32 + mt * 16 + (quad & 1) * 8 + rin;
                int col = k0 + (quad >> 1) * 8;
                uint32_t ad = aBase + row * LDT + col * 2;
                LDM_X4(afh[mt], ad);
                LDM_X4(afl[mt], ad + TILE_B);
            }
#pragma unroll
            for (int nb = 0; nb < 4; nb++) {
                int row = wn * 64 + nb * 16 + (quad >> 1) * 8 + rin;
                int col = k0 + (quad & 1) * 8;
                uint32_t bd = bBase + row * LDT + col * 2;
                LDM_X4(bfh[nb], bd);
                LDM_X4(bfl[nb], bd + TILE_B);
            }
#pragma unroll
            for (int mt = 0; mt < 2; mt++)
#pragma unroll
                for (int nt = 0; nt < 8; nt++) {
                    const uint32_t* bh = &bfh[nt >> 1][(nt & 1) * 2];
                    const uint32_t* bl = &bfl[nt >> 1][(nt & 1) * 2];
                    mma_bf16(acc[mt][nt], afh[mt], bh);
                    mma_bf16(acc[mt][nt], afh[mt], bl);
                    mma_bf16(acc[mt][nt], afl[mt], bh);
                }
        }

        if (c == NC - 1) break;
        __syncthreads();                 // all warps done reading other stage
        GEMM_STS((c + 1) & 1);
        __syncthreads();                 // new stage visible
        if (c + 2 < NC) GEMM_LDG(c + 2);
    }

    // Epilogue: d frag mapping (row = lane>>2 [+8], col = 2*(lane&3) [+1])
    const int lr = lane >> 2;
    const int lc = (lane & 3) * 2;
#pragma unroll
    for (int mt = 0; mt < 2; mt++)
#pragma unroll
        for (int nt = 0; nt < 8; nt++) {
            int row = m0 + wm * 32 + mt * 16 + lr;
            int col = n0 + wn * 64 + nt * 8 + lc;
            *(float2*)(C + (size_t)row * N + col) =
                make_float2(acc[mt][nt][0], acc[mt][nt][1]);
            *(float2*)(C + (size_t)(row + 8) * N + col) =
                make_float2(acc[mt][nt][2], acc[mt][nt][3]);
        }
}

// ---------------------------------------------------------------------------
// RoPE in-place on g_qkv: Q heads [0,NH), K heads [NH, NH+NKV)
// ---------------------------------------------------------------------------
__global__ void rope_kernel(const float* __restrict__ cosT,
                            const float* __restrict__ sinT)
{
    const int bt   = blockIdx.x;
    const int head = blockIdx.y;
    const int d    = threadIdx.x;          // 0..63
    const int t    = bt & (TT - 1);

    size_t base = (size_t)bt * QKVW +
                  (head < NH ? head * HD : KOFF + (head - NH) * HD);
    float c = cosT[t * 64 + d];
    float s = sinT[t * 64 + d];
    float x1 = g_qkv[base + d];
    float x2 = g_qkv[base + d + 64];
    g_qkv[base + d]      = x1 * c - x2 * s;
    g_qkv[base + d + 64] = x1 * s + x2 * c;
}

// ---------------------------------------------------------------------------
// Causal GQA flash attention, fp32 (unchanged this round)
// ---------------------------------------------------------------------------
#define ATT_LDK 132
#define ATT_LDS 66
#define ATT_SMEM_FLOATS (3 * 64 * ATT_LDK + 64 * ATT_LDS + 128)
#define ATT_SMEM_BYTES  (ATT_SMEM_FLOATS * 4)

__global__ void __launch_bounds__(256) attn_kernel()
{
    extern __shared__ float smf[];
    float* Qs     = smf;
    float* Ks     = Qs + 64 * ATT_LDK;
    float* Vs     = Ks + 64 * ATT_LDK;
    float* Ss     = Vs + 64 * ATT_LDK;
    float* corr_s = Ss + 64 * ATT_LDS;
    float* l_s    = corr_s + 64;

    const int q0 = blockIdx.x * 64;
    const int h  = blockIdx.y;
    const int b  = blockIdx.z;
    const int kh = h >> 1;
    const int tid = threadIdx.x;
    const int tc = tid & 15;
    const int tr = tid >> 4;

    {
        const float* qbase = g_qkv + ((size_t)(b * TT + q0)) * QKVW + h * HD;
        for (int idx = tid; idx < 64 * 32; idx += 256) {
            int r  = idx >> 5;
            int c4 = (idx & 31) << 2;
            *(float4*)&Qs[r * ATT_LDK + c4] =
                *(const float4*)(qbase + (size_t)r * QKVW + c4);
        }
    }

    float m_r = -INFINITY, l_r = 0.f;
    float o[4][8];
#pragma unroll
    for (int i = 0; i < 4; i++)
#pragma unroll
        for (int u = 0; u < 8; u++) o[i][u] = 0.f;

    const int ntiles = (q0 >> 6) + 1;
    for (int jt = 0; jt < ntiles; jt++) {
        const int kb = jt << 6;
        __syncthreads();

        {
            const float* kbase = g_qkv + ((size_t)(b * TT + kb)) * QKVW + KOFF + kh * HD;
            const float* vbase = g_qkv + ((size_t)(b * TT + kb)) * QKVW + VOFF + kh * HD;
            for (int idx = tid; idx < 64 * 32; idx += 256) {
                int r  = idx >> 5;
                int c4 = (idx & 31) << 2;
                *(float4*)&Ks[r * ATT_LDK + c4] =
                    *(const float4*)(kbase + (size_t)r * QKVW + c4);
                *(float4*)&Vs[r * ATT_LDK + c4] =
                    *(const float4*)(vbase + (size_t)r * QKVW + c4);
            }
        }
        __syncthreads();

        float s_acc[4][4];
#pragma unroll
        for (int i = 0; i < 4; i++)
#pragma unroll
            for (int j = 0; j < 4; j++) s_acc[i][j] = 0.f;

        for (int d = 0; d < HD; d += 4) {
            float4 qv[4], kv[4];
#pragma unroll
            for (int i = 0; i < 4; i++)
                qv[i] = *(const float4*)&Qs[(tr + 16 * i) * ATT_LDK + d];
#pragma unroll
            for (int j = 0; j < 4; j++)
                kv[j] = *(const float4*)&Ks[(tc + 16 * j) * ATT_LDK + d];
#pragma unroll
            for (int i = 0; i < 4; i++)
#pragma unroll
                for (int j = 0; j < 4; j++) {
                    s_acc[i][j] += qv[i].x * kv[j].x;
                    s_acc[i][j] += qv[i].y * kv[j].y;
                    s_acc[i][j] += qv[i].z * kv[j].z;
                    s_acc[i][j] += qv[i].w * kv[j].w;
                }
        }

        const bool diag = (kb == q0);
#pragma unroll
        for (int i = 0; i < 4; i++)
#pragma unroll
            for (int j = 0; j < 4; j++) {
                int rr = tr + 16 * i, cc = tc + 16 * j;
                float sv = s_acc[i][j] * ATT_SCALE;
                if (diag && cc > rr) sv = -INFINITY;
                Ss[rr * ATT_LDS + cc] = sv;
            }
        __syncthreads();

        if (tid < 64) {
            float tm = -INFINITY;
#pragma unroll 8
            for (int c = 0; c < 64; c++)
                tm = fmaxf(tm, Ss[tid * ATT_LDS + c]);
            float nm  = fmaxf(m_r, tm);
            float cor = __expf(m_r - nm);
            float sum = 0.f;
#pragma unroll 8
            for (int c = 0; c < 64; c++) {
                float p = __expf(Ss[tid * ATT_LDS + c] - nm);
                Ss[tid * ATT_LDS + c] = p;
                sum += p;
            }
            l_r = l_r * cor + sum;
            m_r = nm;
            corr_s[tid] = cor;
            l_s[tid] = l_r;
        }
        __syncthreads();

#pragma unroll
        for (int i = 0; i < 4; i++) {
            float cr = corr_s[tr + 16 * i];
#pragma unroll
            for (int u = 0; u < 8; u++) o[i][u] *= cr;
        }

        for (int kk = 0; kk < 64; kk++) {
            float4 v0 = *(const float4*)&Vs[kk * ATT_LDK + tc * 8];
            float4 v1 = *(const float4*)&Vs[kk * ATT_LDK + tc * 8 + 4];
#pragma unroll
            for (int i = 0; i < 4; i++) {
                float p = Ss[(tr + 16 * i) * ATT_LDS + kk];
                o[i][0] += p * v0.x; o[i][1] += p * v0.y;
                o[i][2] += p * v0.z; o[i][3] += p * v0.w;
                o[i][4] += p * v1.x; o[i][5] += p * v1.y;
                o[i][6] += p * v1.z; o[i][7] += p * v1.w;
            }
        }
    }

#pragma unroll
    for (int i = 0; i < 4; i++) {
        int r = tr + 16 * i;
        float inv = 1.f / l_s[r];
        float* obase = g_attn + ((size_t)(b * TT + q0 + r)) * HIDD + h * HD + tc * 8;
        float4 r0 = make_float4(o[i][0] * inv, o[i][1] * inv, o[i][2] * inv, o[i][3] * inv);
        float4 r1 = make_float4(o[i][4] * inv, o[i][5] * inv, o[i][6] * inv, o[i][7] * inv);
        *(float4*)(obase)     = r0;
        *(float4*)(obase + 4) = r1;
    }
}

// ---------------------------------------------------------------------------
extern "C" void kernel_launch(void* const* d_in, const int* in_sizes, int n_in,
                              void* d_out, int out_size)
{
    const float* hidden = (const float*)d_in[0];
    const float* fcos   = (const float*)d_in[1];
    const float* fsin   = (const float*)d_in[2];
    const float* w_qkv  = (const float*)d_in[6];
    const float* w_o    = (const float*)d_in[7];
    float* out = (float*)d_out;

    float *qkv_ptr, *attn_ptr;
    cudaGetSymbolAddress((void**)&qkv_ptr, g_qkv);
    cudaGetSymbolAddress((void**)&attn_ptr, g_attn);

    cudaFuncSetAttribute(gemm_bf16s_kernel,
                         cudaFuncAttributeMaxDynamicSharedMemorySize, GEMM_SMEM);
    cudaFuncSetAttribute(attn_kernel,
                         cudaFuncAttributeMaxDynamicSharedMemorySize, ATT_SMEM_BYTES);

    const int M = BB * TT;  // 4096

    // 1) QKV projection: [4096,2048] @ [4096,2048]^T -> [4096,4096]
    gemm_bf16s_kernel<<<dim3(QKVW / 128, M / 128), 256, GEMM_SMEM>>>(
        hidden, w_qkv, qkv_ptr, M, QKVW, HIDD);

    // 2) RoPE on Q and K heads (in-place)
    rope_kernel<<<dim3(BB * TT, NH + NKV), 64>>>(fcos, fsin);

    // 3) Causal GQA attention -> g_attn [4096, 2048]
    attn_kernel<<<dim3(TT / 64, NH, BB), 256, ATT_SMEM_BYTES>>>();

    // 4) Output projection: [4096,2048] @ [2048,2048]^T -> d_out
    gemm_bf16s_kernel<<<dim3(HIDD / 128, M / 128), 256, GEMM_SMEM>>>(
        attn_ptr, w_o, out, M, HIDD, HIDD);
}

// round 4
// speedup vs baseline: 3.0265x; 2.1957x over previous
#include <cuda_runtime.h>
#include <cuda_bf16.h>
#include <math.h>
#include <stdint.h>

// Problem constants
#define BB 2
#define TT 2048
#define HIDD 2048
#define NH 16
#define NKV 8
#define HD 128
#define QKVW 4096   // (NH + 2*NKV) * HD
#define KOFF 2048   // NH*HD
#define VOFF 3072   // NH*HD + NKV*HD
#define ATT_SCALE 0.08838834764831845f  // 128^-0.5

// Scratch (allocation-free rule: __device__ globals)
__device__ float g_qkv[(size_t)BB * TT * QKVW];                 // 64 MB fp32
__device__ __nv_bfloat16 g_hid_hi[(size_t)BB * TT * HIDD];
__device__ __nv_bfloat16 g_hid_lo[(size_t)BB * TT * HIDD];
__device__ __nv_bfloat16 g_wqkv_hi[(size_t)QKVW * HIDD];
__device__ __nv_bfloat16 g_wqkv_lo[(size_t)QKVW * HIDD];
__device__ __nv_bfloat16 g_wo_hi[(size_t)HIDD * HIDD];
__device__ __nv_bfloat16 g_wo_lo[(size_t)HIDD * HIDD];
__device__ __nv_bfloat16 g_qkvb_hi[(size_t)BB * TT * QKVW];
__device__ __nv_bfloat16 g_qkvb_lo[(size_t)BB * TT * QKVW];
__device__ __nv_bfloat16 g_attnb_hi[(size_t)BB * TT * HIDD];
__device__ __nv_bfloat16 g_attnb_lo[(size_t)BB * TT * HIDD];

// ---------------------------------------------------------------------------
// Helpers (arch-stable PTX: cp.async + ldmatrix + mma.sync, sm_80 level)
// ---------------------------------------------------------------------------
__device__ __forceinline__ uint32_t smem_u32(const void* p) {
    uint32_t a;
    asm("{ .reg .u64 t; cvta.to.shared.u64 t, %1; cvt.u32.u64 %0, t; }"
        : "=r"(a) : "l"(p));
    return a;
}

// pack two f32 -> bf16x2 (lo half = x, hi half = y), round-to-nearest
__device__ __forceinline__ uint32_t pack_bf2(float x, float y) {
    uint32_t r;
    asm("cvt.rn.bf16x2.f32 %0, %1, %2;" : "=r"(r) : "f"(y), "f"(x));
    return r;
}

#define LDM_X4(r, a)                                                            \
    asm volatile("ldmatrix.sync.aligned.m8n8.x4.shared.b16 {%0,%1,%2,%3}, [%4];"\
        : "=r"((r)[0]), "=r"((r)[1]), "=r"((r)[2]), "=r"((r)[3]) : "r"(a))

#define LDM_X4T(r, a)                                                           \
    asm volatile("ldmatrix.sync.aligned.m8n8.x4.trans.shared.b16 "              \
                 "{%0,%1,%2,%3}, [%4];"                                         \
        : "=r"((r)[0]), "=r"((r)[1]), "=r"((r)[2]), "=r"((r)[3]) : "r"(a))

__device__ __forceinline__ void mma_bf16(float* d, const uint32_t* a, const uint32_t* b) {
    asm volatile(
        "mma.sync.aligned.m16n8k16.row.col.f32.bf16.bf16.f32 "
        "{%0,%1,%2,%3}, {%4,%5,%6,%7}, {%8,%9}, {%0,%1,%2,%3};"
        : "+f"(d[0]), "+f"(d[1]), "+f"(d[2]), "+f"(d[3])
        : "r"(a[0]), "r"(a[1]), "r"(a[2]), "r"(a[3]), "r"(b[0]), "r"(b[1]));
}

#define CP_A16(dst, src)                                                        \
    asm volatile("cp.async.cg.shared.global [%0], [%1], 16;"                    \
        :: "r"(dst), "l"(src))
#define CP_COMMIT() asm volatile("cp.async.commit_group;" ::: "memory")
#define CP_WAIT(n)  asm volatile("cp.async.wait_group %0;" :: "n"(n) : "memory")

// ---------------------------------------------------------------------------
// split: fp32 -> bf16 hi + bf16 lo (x = hi + lo)
// ---------------------------------------------------------------------------
__global__ void split_kernel(const float* __restrict__ src,
                             __nv_bfloat16* __restrict__ hi,
                             __nv_bfloat16* __restrict__ lo, int n4)
{
    int i = blockIdx.x * blockDim.x + threadIdx.x;
    if (i >= n4) return;
    float4 v = ((const float4*)src)[i];
    uint32_t h0 = pack_bf2(v.x, v.y), h1 = pack_bf2(v.z, v.w);
    float lx = v.x - __uint_as_float(h0 << 16);
    float ly = v.y - __uint_as_float(h0 & 0xFFFF0000u);
    float lz = v.z - __uint_as_float(h1 << 16);
    float lw = v.w - __uint_as_float(h1 & 0xFFFF0000u);
    ((uint2*)hi)[i] = make_uint2(h0, h1);
    ((uint2*)lo)[i] = make_uint2(pack_bf2(lx, ly), pack_bf2(lz, lw));
}

// ---------------------------------------------------------------------------
// RoPE (Q,K) + bf16 split of the whole QKV row; Q additionally pre-scaled
// by ATT_SCALE (folded out of the attention score computation).
// grid: (B*T, 8) x 128 threads; each thread one float4 (4 cols).
// ---------------------------------------------------------------------------
__global__ void ropesplit_kernel(const float* __restrict__ cosT,
                                 const float* __restrict__ sinT)
{
    const int bt   = blockIdx.x;
    const int t    = bt & (TT - 1);
    const int slot = blockIdx.y * blockDim.x + threadIdx.x;   // 0..1023
    const int col  = slot * 4;
    const float* row = g_qkv + (size_t)bt * QKVW;
    float4 v = *(const float4*)(row + col);

    if (col < VOFF) {   // Q or K head: rope
        int d  = col & (HD - 1);
        int dd = d & 63;
        float4 c = *(const float4*)(cosT + t * 64 + dd);
        float4 s = *(const float4*)(sinT + t * 64 + dd);
        if (d < 64) {
            float4 x2 = *(const float4*)(row + col + 64);
            v.x = v.x * c.x - x2.x * s.x;
            v.y = v.y * c.y - x2.y * s.y;
            v.z = v.z * c.z - x2.z * s.z;
            v.w = v.w * c.w - x2.w * s.w;
        } else {
            float4 x1 = *(const float4*)(row + col - 64);
            v.x = x1.x * s.x + v.x * c.x;
            v.y = x1.y * s.y + v.y * c.y;
            v.z = x1.z * s.z + v.z * c.z;
            v.w = x1.w * s.w + v.w * c.w;
        }
        if (col < KOFF) {   // Q: fold attention scale
            v.x *= ATT_SCALE; v.y *= ATT_SCALE; v.z *= ATT_SCALE; v.w *= ATT_SCALE;
        }
    }

    uint32_t h0 = pack_bf2(v.x, v.y), h1 = pack_bf2(v.z, v.w);
    float lx = v.x - __uint_as_float(h0 << 16);
    float ly = v.y - __uint_as_float(h0 & 0xFFFF0000u);
    float lz = v.z - __uint_as_float(h1 << 16);
    float lw = v.w - __uint_as_float(h1 & 0xFFFF0000u);
    size_t o = (size_t)bt * (QKVW / 4) + slot;
    ((uint2*)g_qkvb_hi)[o] = make_uint2(h0, h1);
    ((uint2*)g_qkvb_lo)[o] = make_uint2(pack_bf2(lx, ly), pack_bf2(lz, lw));
}

// ---------------------------------------------------------------------------
// Tensor-core NT GEMM on pre-split bf16 hi/lo inputs.
// C[M,N] = (Ah+Al)[M,K] @ (Bh+Bl)[N,K]^T, fp32 accumulate, 3 MMA products.
// CTA 128x128, BK=32, 8 warps (4m x 2n), 4-stage cp.async pipeline.
// SMEM rows: 32 bf16 + 8 pad = 80 B (conflict-free ldmatrix).
// ---------------------------------------------------------------------------
#define GP_TILE 10240            // 128 rows x 80 B
#define GP_STG  (4 * GP_TILE)    // Ah, Al, Bh, Bl
#define GP_SMEM (4 * GP_STG)     // 4 stages = 163840 B

#define GP_ISSUE(c)                                                            \
    do {                                                                       \
        uint32_t sb_ = smb + ((c) & 3) * GP_STG;                               \
        _Pragma("unroll")                                                      \
        for (int i_ = 0; i_ < 8; i_++) {                                       \
            const int t_ = i_ >> 1;                                            \
            int w_ = (i_ & 1) * 256 + tid;                                     \
            int r_ = w_ >> 2, ch_ = w_ & 3;                                    \
            const __nv_bfloat16* src_ =                                        \
                tb[t_] + (size_t)r_ * K + (c) * 32 + ch_ * 8;                  \
            uint32_t dst_ = sb_ + t_ * GP_TILE + r_ * 80 + ch_ * 16;           \
            CP_A16(dst_, src_);                                                \
        }                                                                      \
    } while (0)

__global__ void __launch_bounds__(256, 1) gemm_pre_kernel(
    const __nv_bfloat16* __restrict__ Ah, const __nv_bfloat16* __restrict__ Al,
    const __nv_bfloat16* __restrict__ Bh, const __nv_bfloat16* __restrict__ Bl,
    float* __restrict__ C, int M, int N, int K)
{
    extern __shared__ char sm[];
    const uint32_t smb = smem_u32(sm);
    const int tid = threadIdx.x;
    const int wid = tid >> 5, lane = tid & 31;
    const int m0 = blockIdx.y * 128, n0 = blockIdx.x * 128;
    const int wm = wid & 3, wn = wid >> 2;
    const int quad = lane >> 3, rin = lane & 7;

    const __nv_bfloat16* tb[4] = {
        Ah + (size_t)m0 * K, Al + (size_t)m0 * K,
        Bh + (size_t)n0 * K, Bl + (size_t)n0 * K };
    const int NC = K / 32;

    float acc[2][8][4];
#pragma unroll
    for (int i = 0; i < 2; i++)
#pragma unroll
        for (int j = 0; j < 8; j++)
#pragma unroll
            for (int u = 0; u < 4; u++) acc[i][j][u] = 0.f;

    GP_ISSUE(0); CP_COMMIT();
    GP_ISSUE(1); CP_COMMIT();
    GP_ISSUE(2); CP_COMMIT();

    for (int c = 0; c < NC; c++) {
        CP_WAIT(2);
        __syncthreads();

        const uint32_t aBase = smb + (c & 3) * GP_STG;
        const uint32_t bBase = aBase + 2 * GP_TILE;
#pragma unroll
        for (int ks = 0; ks < 2; ks++) {
            const int k0 = ks * 16;
            uint32_t afh[2][4], afl[2][4], bfh[4][4], bfl[4][4];
#pragma unroll
            for (int mt = 0; mt < 2; mt++) {
                int row = wm * 32 + mt * 16 + (quad & 1) * 8 + rin;
                int col = k0 + (quad >> 1) * 8;
                uint32_t ad = aBase + row * 80 + col * 2;
                LDM_X4(afh[mt], ad);
                LDM_X4(afl[mt], ad + GP_TILE);
            }
#pragma unroll
            for (int nb = 0; nb < 4; nb++) {
                int row = wn * 64 + nb * 16 + (quad >> 1) * 8 + rin;
                int col = k0 + (quad & 1) * 8;
                uint32_t bd = bBase + row * 80 + col * 2;
                LDM_X4(bfh[nb], bd);
                LDM_X4(bfl[nb], bd + GP_TILE);
            }
#pragma unroll
            for (int mt = 0; mt < 2; mt++)
#pragma unroll
                for (int nt = 0; nt < 8; nt++) {
                    const uint32_t* bh = &bfh[nt >> 1][(nt & 1) * 2];
                    const uint32_t* bl = &bfl[nt >> 1][(nt & 1) * 2];
                    mma_bf16(acc[mt][nt], afh[mt], bh);
                    mma_bf16(acc[mt][nt], afh[mt], bl);
                    mma_bf16(acc[mt][nt], afl[mt], bh);
                }
        }

        if (c + 3 < NC) GP_ISSUE(c + 3);
        CP_COMMIT();
    }

    const int lr = lane >> 2;
    const int lc = (lane & 3) * 2;
#pragma unroll
    for (int mt = 0; mt < 2; mt++)
#pragma unroll
        for (int nt = 0; nt < 8; nt++) {
            int row = m0 + wm * 32 + mt * 16 + lr;
            int col = n0 + wn * 64 + nt * 8 + lc;
            *(float2*)(C + (size_t)row * N + col) =
                make_float2(acc[mt][nt][0], acc[mt][nt][1]);
            *(float2*)(C + (size_t)(row + 8) * N + col) =
                make_float2(acc[mt][nt][2], acc[mt][nt][3]);
        }
}

// ---------------------------------------------------------------------------
// Tensor-core causal GQA flash attention (bf16 split, fp32 accum).
// CTA: 64 Q rows x (head, batch); 4 warps, each warp owns 16 Q rows.
// Per kv tile (64): S = Q@K^T (MMA), register online softmax, O += P@V (MMA).
// SMEM rows: 128 bf16 + 8 pad = 272 B. Output written pre-split bf16 hi/lo.
// ---------------------------------------------------------------------------
#define AQLD  272
#define ATILE 17408                 // 64 rows x 272 B
#define A_KH  (2 * ATILE)
#define A_VH  (4 * ATILE)
#define ATT_SMEM (6 * ATILE)        // 104448 B

__global__ void __launch_bounds__(128, 2) attn_kernel()
{
    extern __shared__ char sm[];
    const uint32_t smb = smem_u32(sm);
    const int tid = threadIdx.x;
    const int wid = tid >> 5, lane = tid & 31;
    const int q0 = blockIdx.x * 64;
    const int h = blockIdx.y, b = blockIdx.z;
    const int khh = h >> 1;                 // GQA: n_rep = 2

    const int l8  = (lane >> 3) & 1;
    const int l16 = lane >> 4;
    const int rin = lane & 7;

    // ---- load Q tile hi/lo once (cp.async) ----
    {
        const __nv_bfloat16* qh = g_qkvb_hi + ((size_t)(b * TT + q0)) * QKVW + h * HD;
        const __nv_bfloat16* ql = g_qkvb_lo + ((size_t)(b * TT + q0)) * QKVW + h * HD;
#pragma unroll
        for (int i = 0; i < 16; i++) {
            const int bufl = i >> 3;
            int w = (i & 7) * 128 + tid;
            int r = w >> 4, ch = w & 15;
            const __nv_bfloat16* src = (bufl ? ql : qh) + (size_t)r * QKVW + ch * 8;
            uint32_t dst = smb + bufl * ATILE + r * AQLD + ch * 16;
            CP_A16(dst, src);
        }
        CP_COMMIT();
    }

    float o[16][4];
#pragma unroll
    for (int i = 0; i < 16; i++)
#pragma unroll
        for (int u = 0; u < 4; u++) o[i][u] = 0.f;
    float m0r = -1e30f, m1r = -1e30f, l0 = 0.f, l1 = 0.f;

    const size_t bbase = (size_t)(b * TT);
    const int ntiles = (q0 >> 6) + 1;

    for (int jt = 0; jt < ntiles; jt++) {
        const int kb = jt << 6;
        __syncthreads();   // everyone done reading previous K/V tiles

        // ---- load K,V hi/lo tiles ----
        {
            const size_t rb = (bbase + kb) * QKVW;
            const __nv_bfloat16* s0 = g_qkvb_hi + rb + KOFF + khh * HD;
            const __nv_bfloat16* s1 = g_qkvb_lo + rb + KOFF + khh * HD;
            const __nv_bfloat16* s2 = g_qkvb_hi + rb + VOFF + khh * HD;
            const __nv_bfloat16* s3 = g_qkvb_lo + rb + VOFF + khh * HD;
#pragma unroll
            for (int i = 0; i < 32; i++) {
                const int t = i >> 3;
                int w = (i & 7) * 128 + tid;
                int r = w >> 4, ch = w & 15;
                const __nv_bfloat16* src =
                    (t == 0 ? s0 : t == 1 ? s1 : t == 2 ? s2 : s3)
                    + (size_t)r * QKVW + ch * 8;
                uint32_t dst = smb + A_KH + t * ATILE + r * AQLD + ch * 16;
                CP_A16(dst, src);
            }
            CP_COMMIT();
        }
        CP_WAIT(0);
        __syncthreads();

        // ---- S = Q @ K^T  (Q pre-scaled by ATT_SCALE) ----
        float s[8][4];
#pragma unroll
        for (int i = 0; i < 8; i++)
#pragma unroll
            for (int u = 0; u < 4; u++) s[i][u] = 0.f;

#pragma unroll
        for (int ks = 0; ks < 8; ks++) {
            const int k0 = ks * 16;
            uint32_t aqh[4], aql[4];
            uint32_t aaddr = smb + (wid * 16 + l8 * 8 + rin) * AQLD + (k0 + l16 * 8) * 2;
            LDM_X4(aqh, aaddr);
            LDM_X4(aql, aaddr + ATILE);
#pragma unroll
            for (int nb = 0; nb < 4; nb++) {
                uint32_t bh4[4], bl4[4];
                uint32_t baddr = smb + A_KH + (nb * 16 + l16 * 8 + rin) * AQLD
                               + (k0 + l8 * 8) * 2;
                LDM_X4(bh4, baddr);
                LDM_X4(bl4, baddr + ATILE);
#pragma unroll
                for (int hf = 0; hf < 2; hf++) {
                    mma_bf16(s[nb * 2 + hf], aqh, &bh4[hf * 2]);
                    mma_bf16(s[nb * 2 + hf], aqh, &bl4[hf * 2]);
                    mma_bf16(s[nb * 2 + hf], aql, &bh4[hf * 2]);
                }
            }
        }

        // ---- causal mask on the diagonal tile ----
        if (kb == q0) {
            const int r0l = wid * 16 + (lane >> 2);
#pragma unroll
            for (int nt = 0; nt < 8; nt++) {
                int c0 = nt * 8 + 2 * (lane & 3);
                if (c0     > r0l)     s[nt][0] = -1e30f;
                if (c0 + 1 > r0l)     s[nt][1] = -1e30f;
                if (c0     > r0l + 8) s[nt][2] = -1e30f;
                if (c0 + 1 > r0l + 8) s[nt][3] = -1e30f;
            }
        }

        // ---- register online softmax (rows lr and lr+8) ----
        float tm0 = -1e30f, tm1 = -1e30f;
#pragma unroll
        for (int nt = 0; nt < 8; nt++) {
            tm0 = fmaxf(tm0, fmaxf(s[nt][0], s[nt][1]));
            tm1 = fmaxf(tm1, fmaxf(s[nt][2], s[nt][3]));
        }
        tm0 = fmaxf(tm0, __shfl_xor_sync(0xffffffffu, tm0, 1));
        tm0 = fmaxf(tm0, __shfl_xor_sync(0xffffffffu, tm0, 2));
        tm1 = fmaxf(tm1, __shfl_xor_sync(0xffffffffu, tm1, 1));
        tm1 = fmaxf(tm1, __shfl_xor_sync(0xffffffffu, tm1, 2));
        float nm0 = fmaxf(m0r, tm0), nm1 = fmaxf(m1r, tm1);
        float cor0 = __expf(m0r - nm0), cor1 = __expf(m1r - nm1);
        m0r = nm0; m1r = nm1;

        float sum0 = 0.f, sum1 = 0.f;
#pragma unroll
        for (int nt = 0; nt < 8; nt++) {
            s[nt][0] = __expf(s[nt][0] - nm0);
            s[nt][1] = __expf(s[nt][1] - nm0);
            s[nt][2] = __expf(s[nt][2] - nm1);
            s[nt][3] = __expf(s[nt][3] - nm1);
            sum0 += s[nt][0] + s[nt][1];
            sum1 += s[nt][2] + s[nt][3];
        }
        sum0 += __shfl_xor_sync(0xffffffffu, sum0, 1);
        sum0 += __shfl_xor_sync(0xffffffffu, sum0, 2);
        sum1 += __shfl_xor_sync(0xffffffffu, sum1, 1);
        sum1 += __shfl_xor_sync(0xffffffffu, sum1, 2);
        l0 = l0 * cor0 + sum0;
        l1 = l1 * cor1 + sum1;

#pragma unroll
        for (int nt = 0; nt < 16; nt++) {
            o[nt][0] *= cor0; o[nt][1] *= cor0;
            o[nt][2] *= cor1; o[nt][3] *= cor1;
        }

        // ---- O += P @ V : P frags built in-register from S frags ----
#pragma unroll
        for (int kk = 0; kk < 4; kk++) {
            uint32_t ah[4], al[4];
            {
                float v0 = s[2 * kk][0],     v1 = s[2 * kk][1];
                float v2 = s[2 * kk][2],     v3 = s[2 * kk][3];
                float w0 = s[2 * kk + 1][0], w1 = s[2 * kk + 1][1];
                float w2 = s[2 * kk + 1][2], w3 = s[2 * kk + 1][3];
                ah[0] = pack_bf2(v0, v1); ah[1] = pack_bf2(v2, v3);
                ah[2] = pack_bf2(w0, w1); ah[3] = pack_bf2(w2, w3);
                al[0] = pack_bf2(v0 - __uint_as_float(ah[0] << 16),
                                 v1 - __uint_as_float(ah[0] & 0xFFFF0000u));
                al[1] = pack_bf2(v2 - __uint_as_float(ah[1] << 16),
                                 v3 - __uint_as_float(ah[1] & 0xFFFF0000u));
                al[2] = pack_bf2(w0 - __uint_as_float(ah[2] << 16),
                                 w1 - __uint_as_float(ah[2] & 0xFFFF0000u));
                al[3] = pack_bf2(w2 - __uint_as_float(ah[3] << 16),
                                 w3 - __uint_as_float(ah[3] & 0xFFFF0000u));
            }
#pragma unroll
            for (int nb = 0; nb < 8; nb++) {
                uint32_t vh4[4], vl4[4];
                uint32_t vaddr = smb + A_VH + (kk * 16 + l8 * 8 + rin) * AQLD
                               + (nb * 16 + l16 * 8) * 2;
                LDM_X4T(vh4, vaddr);
                LDM_X4T(vl4, vaddr + ATILE);
#pragma unroll
                for (int hf = 0; hf < 2; hf++) {
                    mma_bf16(o[nb * 2 + hf], ah, &vh4[hf * 2]);
                    mma_bf16(o[nb * 2 + hf], ah, &vl4[hf * 2]);
                    mma_bf16(o[nb * 2 + hf], al, &vh4[hf * 2]);
                }
            }
        }
    }

    // ---- epilogue: normalize + bf16-split store for the O-projection ----
    float inv0 = 1.f / l0, inv1 = 1.f / l1;
    const size_t r0 = bbase + q0 + wid * 16 + (lane >> 2);
    const int gc = h * HD + 2 * (lane & 3);
#pragma unroll
    for (int nt = 0; nt < 16; nt++) {
        int col = gc + nt * 8;
        float v0 = o[nt][0] * inv0, v1 = o[nt][1] * inv0;
        uint32_t hh = pack_bf2(v0, v1);
        uint32_t ll = pack_bf2(v0 - __uint_as_float(hh << 16),
                               v1 - __uint_as_float(hh & 0xFFFF0000u));
        *(uint32_t*)(g_attnb_hi + r0 * HIDD + col) = hh;
        *(uint32_t*)(g_attnb_lo + r0 * HIDD + col) = ll;
        float v2 = o[nt][2] * inv1, v3 = o[nt][3] * inv1;
        hh = pack_bf2(v2, v3);
        ll = pack_bf2(v2 - __uint_as_float(hh << 16),
                      v3 - __uint_as_float(hh & 0xFFFF0000u));
        *(uint32_t*)(g_attnb_hi + (r0 + 8) * HIDD + col) = hh;
        *(uint32_t*)(g_attnb_lo + (r0 + 8) * HIDD + col) = ll;
    }
}

// ---------------------------------------------------------------------------
extern "C" void kernel_launch(void* const* d_in, const int* in_sizes, int n_in,
                              void* d_out, int out_size)
{
    const float* hidden = (const float*)d_in[0];
    const float* fcos   = (const float*)d_in[1];
    const float* fsin   = (const float*)d_in[2];
    const float* w_qkv  = (const float*)d_in[6];
    const float* w_o    = (const float*)d_in[7];
    float* out = (float*)d_out;

    float* qkv_f;
    __nv_bfloat16 *hid_hi, *hid_lo, *wqkv_hi, *wqkv_lo, *wo_hi, *wo_lo;
    __nv_bfloat16 *attn_hi, *attn_lo;
    cudaGetSymbolAddress((void**)&qkv_f,   g_qkv);
    cudaGetSymbolAddress((void**)&hid_hi,  g_hid_hi);
    cudaGetSymbolAddress((void**)&hid_lo,  g_hid_lo);
    cudaGetSymbolAddress((void**)&wqkv_hi, g_wqkv_hi);
    cudaGetSymbolAddress((void**)&wqkv_lo, g_wqkv_lo);
    cudaGetSymbolAddress((void**)&wo_hi,   g_wo_hi);
    cudaGetSymbolAddress((void**)&wo_lo,   g_wo_lo);
    cudaGetSymbolAddress((void**)&attn_hi, g_attnb_hi);
    cudaGetSymbolAddress((void**)&attn_lo, g_attnb_lo);

    cudaFuncSetAttribute(gemm_pre_kernel,
                         cudaFuncAttributeMaxDynamicSharedMemorySize, GP_SMEM);
    cudaFuncSetAttribute(attn_kernel,
                         cudaFuncAttributeMaxDynamicSharedMemorySize, ATT_SMEM);

    const int M = BB * TT;  // 4096

    // 0) split fp32 operands into bf16 hi/lo
    split_kernel<<<8192, 256>>>(hidden, hid_hi, hid_lo, (BB * TT * HIDD) / 4);
    split_kernel<<<8192, 256>>>(w_qkv, wqkv_hi, wqkv_lo, (QKVW * HIDD) / 4);
    split_kernel<<<4096, 256>>>(w_o, wo_hi, wo_lo, (HIDD * HIDD) / 4);

    // 1) QKV projection -> g_qkv fp32
    gemm_pre_kernel<<<dim3(QKVW / 128, M / 128), 256, GP_SMEM>>>(
        hid_hi, hid_lo, wqkv_hi, wqkv_lo, qkv_f, M, QKVW, HIDD);

    // 2) RoPE + scale-fold + bf16 split -> g_qkvb
    ropesplit_kernel<<<dim3(BB * TT, 8), 128>>>(fcos, fsin);

    // 3) causal GQA attention (tensor cores) -> g_attnb bf16 hi/lo
    attn_kernel<<<dim3(TT / 64, NH, BB), 128, ATT_SMEM>>>();

    // 4) output projection -> d_out fp32
    gemm_pre_kernel<<<dim3(HIDD / 128, M / 128), 256, GP_SMEM>>>(
        attn_hi, attn_lo, wo_hi, wo_lo, out, M, HIDD, HIDD);
}

// round 5
// speedup vs baseline: 3.0920x; 1.0217x over previous
#include <cuda_runtime.h>
#include <cuda_bf16.h>
#include <math.h>
#include <stdint.h>

// Problem constants
#define BB 2
#define TT 2048
#define HIDD 2048
#define NH 16
#define NKV 8
#define HD 128
#define QKVW 4096   // (NH + 2*NKV) * HD
#define KOFF 2048   // NH*HD
#define VOFF 3072   // NH*HD + NKV*HD
#define ATT_SCALE 0.08838834764831845f  // 128^-0.5

// Scratch (allocation-free rule: __device__ globals)
__device__ float g_qkv[(size_t)BB * TT * QKVW];                 // 64 MB fp32
__device__ __nv_bfloat16 g_hid_hi[(size_t)BB * TT * HIDD];
__device__ __nv_bfloat16 g_hid_lo[(size_t)BB * TT * HIDD];
__device__ __nv_bfloat16 g_wqkv_hi[(size_t)QKVW * HIDD];
__device__ __nv_bfloat16 g_wqkv_lo[(size_t)QKVW * HIDD];
__device__ __nv_bfloat16 g_wo_hi[(size_t)HIDD * HIDD];
__device__ __nv_bfloat16 g_wo_lo[(size_t)HIDD * HIDD];
__device__ __nv_bfloat16 g_qkvb_hi[(size_t)BB * TT * QKVW];
__device__ __nv_bfloat16 g_qkvb_lo[(size_t)BB * TT * QKVW];
__device__ __nv_bfloat16 g_attnb_hi[(size_t)BB * TT * HIDD];
__device__ __nv_bfloat16 g_attnb_lo[(size_t)BB * TT * HIDD];

// ---------------------------------------------------------------------------
// Helpers (arch-stable PTX: cp.async + ldmatrix + mma.sync, sm_80 level)
// ---------------------------------------------------------------------------
__device__ __forceinline__ uint32_t smem_u32(const void* p) {
    uint32_t a;
    asm("{ .reg .u64 t; cvta.to.shared.u64 t, %1; cvt.u32.u64 %0, t; }"
        : "=r"(a) : "l"(p));
    return a;
}

// pack two f32 -> bf16x2 (lo half = x, hi half = y), round-to-nearest
__device__ __forceinline__ uint32_t pack_bf2(float x, float y) {
    uint32_t r;
    asm("cvt.rn.bf16x2.f32 %0, %1, %2;" : "=r"(r) : "f"(y), "f"(x));
    return r;
}

#define LDM_X4(r, a)                                                            \
    asm volatile("ldmatrix.sync.aligned.m8n8.x4.shared.b16 {%0,%1,%2,%3}, [%4];"\
        : "=r"((r)[0]), "=r"((r)[1]), "=r"((r)[2]), "=r"((r)[3]) : "r"(a))

#define LDM_X4T(r, a)                                                           \
    asm volatile("ldmatrix.sync.aligned.m8n8.x4.trans.shared.b16 "              \
                 "{%0,%1,%2,%3}, [%4];"                                         \
        : "=r"((r)[0]), "=r"((r)[1]), "=r"((r)[2]), "=r"((r)[3]) : "r"(a))

__device__ __forceinline__ void mma_bf16(float* d, const uint32_t* a, const uint32_t* b) {
    asm volatile(
        "mma.sync.aligned.m16n8k16.row.col.f32.bf16.bf16.f32 "
        "{%0,%1,%2,%3}, {%4,%5,%6,%7}, {%8,%9}, {%0,%1,%2,%3};"
        : "+f"(d[0]), "+f"(d[1]), "+f"(d[2]), "+f"(d[3])
        : "r"(a[0]), "r"(a[1]), "r"(a[2]), "r"(a[3]), "r"(b[0]), "r"(b[1]));
}

#define CP_A16(dst, src)                                                        \
    asm volatile("cp.async.cg.shared.global [%0], [%1], 16;"                    \
        :: "r"(dst), "l"(src))
#define CP_COMMIT() asm volatile("cp.async.commit_group;" ::: "memory")
#define CP_WAIT(n)  asm volatile("cp.async.wait_group %0;" :: "n"(n) : "memory")

// ---------------------------------------------------------------------------
// split: fp32 -> bf16 hi + bf16 lo (x = hi + lo)
// ---------------------------------------------------------------------------
__global__ void split_kernel(const float* __restrict__ src,
                             __nv_bfloat16* __restrict__ hi,
                             __nv_bfloat16* __restrict__ lo, int n4)
{
    int i = blockIdx.x * blockDim.x + threadIdx.x;
    if (i >= n4) return;
    float4 v = ((const float4*)src)[i];
    uint32_t h0 = pack_bf2(v.x, v.y), h1 = pack_bf2(v.z, v.w);
    float lx = v.x - __uint_as_float(h0 << 16);
    float ly = v.y - __uint_as_float(h0 & 0xFFFF0000u);
    float lz = v.z - __uint_as_float(h1 << 16);
    float lw = v.w - __uint_as_float(h1 & 0xFFFF0000u);
    ((uint2*)hi)[i] = make_uint2(h0, h1);
    ((uint2*)lo)[i] = make_uint2(pack_bf2(lx, ly), pack_bf2(lz, lw));
}

// ---------------------------------------------------------------------------
// RoPE (Q,K) + bf16 split of the whole QKV row; Q additionally pre-scaled
// by ATT_SCALE (folded out of the attention score computation).
// ---------------------------------------------------------------------------
__global__ void ropesplit_kernel(const float* __restrict__ cosT,
                                 const float* __restrict__ sinT)
{
    const int bt   = blockIdx.x;
    const int t    = bt & (TT - 1);
    const int slot = blockIdx.y * blockDim.x + threadIdx.x;   // 0..1023
    const int col  = slot * 4;
    const float* row = g_qkv + (size_t)bt * QKVW;
    float4 v = *(const float4*)(row + col);

    if (col < VOFF) {   // Q or K head: rope
        int d  = col & (HD - 1);
        int dd = d & 63;
        float4 c = *(const float4*)(cosT + t * 64 + dd);
        float4 s = *(const float4*)(sinT + t * 64 + dd);
        if (d < 64) {
            float4 x2 = *(const float4*)(row + col + 64);
            v.x = v.x * c.x - x2.x * s.x;
            v.y = v.y * c.y - x2.y * s.y;
            v.z = v.z * c.z - x2.z * s.z;
            v.w = v.w * c.w - x2.w * s.w;
        } else {
            float4 x1 = *(const float4*)(row + col - 64);
            v.x = x1.x * s.x + v.x * c.x;
            v.y = x1.y * s.y + v.y * c.y;
            v.z = x1.z * s.z + v.z * c.z;
            v.w = x1.w * s.w + v.w * c.w;
        }
        if (col < KOFF) {   // Q: fold attention scale
            v.x *= ATT_SCALE; v.y *= ATT_SCALE; v.z *= ATT_SCALE; v.w *= ATT_SCALE;
        }
    }

    uint32_t h0 = pack_bf2(v.x, v.y), h1 = pack_bf2(v.z, v.w);
    float lx = v.x - __uint_as_float(h0 << 16);
    float ly = v.y - __uint_as_float(h0 & 0xFFFF0000u);
    float lz = v.z - __uint_as_float(h1 << 16);
    float lw = v.w - __uint_as_float(h1 & 0xFFFF0000u);
    size_t o = (size_t)bt * (QKVW / 4) + slot;
    ((uint2*)g_qkvb_hi)[o] = make_uint2(h0, h1);
    ((uint2*)g_qkvb_lo)[o] = make_uint2(pack_bf2(lx, ly), pack_bf2(lz, lw));
}

// ---------------------------------------------------------------------------
// Tensor-core NT GEMM on pre-split bf16 hi/lo inputs.
// C[M,N] = (Ah+Al)[M,K] @ (Bh+Bl)[N,K]^T, fp32 accumulate, 3 MMA products.
// CTA 256x128, BK=32, 8 warps (4m x 2n), 64x64 warp tiles (MMA:ldmatrix = 6),
// 3-stage cp.async pipeline. SMEM rows: 32 bf16 + 8 pad = 80 B.
// ---------------------------------------------------------------------------
#define GQ_AT (256 * 80)            // 20480 per A buf (hi or lo)
#define GQ_BT (128 * 80)            // 10240 per B buf
#define GQ_STG (2 * GQ_AT + 2 * GQ_BT)   // 61440 per stage
#define GQ_SMEM (3 * GQ_STG)             // 184320

#define GQ_ISSUE(c)                                                            \
    do {                                                                       \
        uint32_t sb_ = smb + ((c) % 3) * GQ_STG;                               \
        _Pragma("unroll")                                                      \
        for (int i_ = 0; i_ < 8; i_++) {     /* A hi/lo: 2 bufs x 4 */         \
            const int bu_ = i_ >> 2;                                           \
            int w_ = (i_ & 3) * 256 + tid;                                     \
            int r_ = w_ >> 2, ch_ = w_ & 3;                                    \
            CP_A16(sb_ + bu_ * GQ_AT + r_ * 80 + ch_ * 16,                     \
                   ta[bu_] + (size_t)r_ * K + (c) * 32 + ch_ * 8);             \
        }                                                                      \
        _Pragma("unroll")                                                      \
        for (int i_ = 0; i_ < 4; i_++) {     /* B hi/lo: 2 bufs x 2 */         \
            const int bu_ = i_ >> 1;                                           \
            int w_ = (i_ & 1) * 256 + tid;                                     \
            int r_ = w_ >> 2, ch_ = w_ & 3;                                    \
            CP_A16(sb_ + 2 * GQ_AT + bu_ * GQ_BT + r_ * 80 + ch_ * 16,         \
                   tbp[bu_] + (size_t)r_ * K + (c) * 32 + ch_ * 8);            \
        }                                                                      \
    } while (0)

__global__ void __launch_bounds__(256, 1) gemm_pre_kernel(
    const __nv_bfloat16* __restrict__ Ah, const __nv_bfloat16* __restrict__ Al,
    const __nv_bfloat16* __restrict__ Bh, const __nv_bfloat16* __restrict__ Bl,
    float* __restrict__ C, int M, int N, int K)
{
    extern __shared__ char sm[];
    const uint32_t smb = smem_u32(sm);
    const int tid = threadIdx.x;
    const int wid = tid >> 5, lane = tid & 31;
    const int m0 = blockIdx.y * 256, n0 = blockIdx.x * 128;
    const int wm = wid & 3, wn = wid >> 2;          // 4m x 2n, 64x64 each
    const int quad = lane >> 3, rin = lane & 7;

    const __nv_bfloat16* ta[2]  = { Ah + (size_t)m0 * K, Al + (size_t)m0 * K };
    const __nv_bfloat16* tbp[2] = { Bh + (size_t)n0 * K, Bl + (size_t)n0 * K };
    const int NC = K / 32;

    float acc[4][8][4];
#pragma unroll
    for (int i = 0; i < 4; i++)
#pragma unroll
        for (int j = 0; j < 8; j++)
#pragma unroll
            for (int u = 0; u < 4; u++) acc[i][j][u] = 0.f;

    GQ_ISSUE(0); CP_COMMIT();
    GQ_ISSUE(1); CP_COMMIT();

    for (int c = 0; c < NC; c++) {
        CP_WAIT(1);
        __syncthreads();

        const uint32_t aBase = smb + (c % 3) * GQ_STG;
        const uint32_t bBase = aBase + 2 * GQ_AT;
#pragma unroll
        for (int ks = 0; ks < 2; ks++) {
            const int k0 = ks * 16;
            uint32_t afh[4][4], afl[4][4];
#pragma unroll
            for (int mt = 0; mt < 4; mt++) {
                int row = wm * 64 + mt * 16 + (quad & 1) * 8 + rin;
                int col = k0 + (quad >> 1) * 8;
                uint32_t ad = aBase + row * 80 + col * 2;
                LDM_X4(afh[mt], ad);
                LDM_X4(afl[mt], ad + GQ_AT);
            }
#pragma unroll
            for (int nb = 0; nb < 4; nb++) {
                uint32_t bh4[4], bl4[4];
                int rowb = wn * 64 + nb * 16 + (quad >> 1) * 8 + rin;
                int colb = k0 + (quad & 1) * 8;
                uint32_t bd = bBase + rowb * 80 + colb * 2;
                LDM_X4(bh4, bd);
                LDM_X4(bl4, bd + GQ_BT);
#pragma unroll
                for (int mt = 0; mt < 4; mt++)
#pragma unroll
                    for (int hf = 0; hf < 2; hf++) {
                        mma_bf16(acc[mt][nb * 2 + hf], afh[mt], &bh4[hf * 2]);
                        mma_bf16(acc[mt][nb * 2 + hf], afh[mt], &bl4[hf * 2]);
                        mma_bf16(acc[mt][nb * 2 + hf], afl[mt], &bh4[hf * 2]);
                    }
            }
        }

        if (c + 2 < NC) GQ_ISSUE(c + 2);
        CP_COMMIT();
    }

    const int lr = lane >> 2;
    const int lc = (lane & 3) * 2;
#pragma unroll
    for (int mt = 0; mt < 4; mt++)
#pragma unroll
        for (int nt = 0; nt < 8; nt++) {
            int row = m0 + wm * 64 + mt * 16 + lr;
            int col = n0 + wn * 64 + nt * 8 + lc;
            *(float2*)(C + (size_t)row * N + col) =
                make_float2(acc[mt][nt][0], acc[mt][nt][1]);
            *(float2*)(C + (size_t)(row + 8) * N + col) =
                make_float2(acc[mt][nt][2], acc[mt][nt][3]);
        }
}

// ---------------------------------------------------------------------------
// Tensor-core causal GQA flash attention (bf16 split, fp32 accum).
// CTA: 64 Q rows x (head, batch); 4 warps, each warp owns 16 Q rows.
// ---------------------------------------------------------------------------
#define AQLD  272
#define ATILE 17408                 // 64 rows x 272 B
#define A_KH  (2 * ATILE)
#define A_VH  (4 * ATILE)
#define ATT_SMEM (6 * ATILE)        // 104448 B

__global__ void __launch_bounds__(128, 2) attn_kernel()
{
    extern __shared__ char sm[];
    const uint32_t smb = smem_u32(sm);
    const int tid = threadIdx.x;
    const int wid = tid >> 5, lane = tid & 31;
    const int q0 = blockIdx.x * 64;
    const int h = blockIdx.y, b = blockIdx.z;
    const int khh = h >> 1;                 // GQA: n_rep = 2

    const int l8  = (lane >> 3) & 1;
    const int l16 = lane >> 4;
    const int rin = lane & 7;

    // ---- load Q tile hi/lo once (cp.async) ----
    {
        const __nv_bfloat16* qh = g_qkvb_hi + ((size_t)(b * TT + q0)) * QKVW + h * HD;
        const __nv_bfloat16* ql = g_qkvb_lo + ((size_t)(b * TT + q0)) * QKVW + h * HD;
#pragma unroll
        for (int i = 0; i < 16; i++) {
            const int bufl = i >> 3;
            int w = (i & 7) * 128 + tid;
            int r = w >> 4, ch = w & 15;
            const __nv_bfloat16* src = (bufl ? ql : qh) + (size_t)r * QKVW + ch * 8;
            uint32_t dst = smb + bufl * ATILE + r * AQLD + ch * 16;
            CP_A16(dst, src);
        }
        CP_COMMIT();
    }

    float o[16][4];
#pragma unroll
    for (int i = 0; i < 16; i++)
#pragma unroll
        for (int u = 0; u < 4; u++) o[i][u] = 0.f;
    float m0r = -1e30f, m1r = -1e30f, l0 = 0.f, l1 = 0.f;

    const size_t bbase = (size_t)(b * TT);
    const int ntiles = (q0 >> 6) + 1;

    for (int jt = 0; jt < ntiles; jt++) {
        const int kb = jt << 6;
        __syncthreads();   // everyone done reading previous K/V tiles

        // ---- load K,V hi/lo tiles ----
        {
            const size_t rb = (bbase + kb) * QKVW;
            const __nv_bfloat16* s0 = g_qkvb_hi + rb + KOFF + khh * HD;
            const __nv_bfloat16* s1 = g_qkvb_lo + rb + KOFF + khh * HD;
            const __nv_bfloat16* s2 = g_qkvb_hi + rb + VOFF + khh * HD;
            const __nv_bfloat16* s3 = g_qkvb_lo + rb + VOFF + khh * HD;
#pragma unroll
            for (int i = 0; i < 32; i++) {
                const int t = i >> 3;
                int w = (i & 7) * 128 + tid;
                int r = w >> 4, ch = w & 15;
                const __nv_bfloat16* src =
                    (t == 0 ? s0 : t == 1 ? s1 : t == 2 ? s2 : s3)
                    + (size_t)r * QKVW + ch * 8;
                uint32_t dst = smb + A_KH + t * ATILE + r * AQLD + ch * 16;
                CP_A16(dst, src);
            }
            CP_COMMIT();
        }
        CP_WAIT(0);
        __syncthreads();

        // ---- S = Q @ K^T  (Q pre-scaled by ATT_SCALE) ----
        float s[8][4];
#pragma unroll
        for (int i = 0; i < 8; i++)
#pragma unroll
            for (int u = 0; u < 4; u++) s[i][u] = 0.f;

#pragma unroll
        for (int ks = 0; ks < 8; ks++) {
            const int k0 = ks * 16;
            uint32_t aqh[4], aql[4];
            uint32_t aaddr = smb + (wid * 16 + l8 * 8 + rin) * AQLD + (k0 + l16 * 8) * 2;
            LDM_X4(aqh, aaddr);
            LDM_X4(aql, aaddr + ATILE);
#pragma unroll
            for (int nb = 0; nb < 4; nb++) {
                uint32_t bh4[4], bl4[4];
                uint32_t baddr = smb + A_KH + (nb * 16 + l16 * 8 + rin) * AQLD
                               + (k0 + l8 * 8) * 2;
                LDM_X4(bh4, baddr);
                LDM_X4(bl4, baddr + ATILE);
#pragma unroll
                for (int hf = 0; hf < 2; hf++) {
                    mma_bf16(s[nb * 2 + hf], aqh, &bh4[hf * 2]);
                    mma_bf16(s[nb * 2 + hf], aqh, &bl4[hf * 2]);
                    mma_bf16(s[nb * 2 + hf], aql, &bh4[hf * 2]);
                }
            }
        }

        // ---- causal mask on the diagonal tile ----
        if (kb == q0) {
            const int r0l = wid * 16 + (lane >> 2);
#pragma unroll
            for (int nt = 0; nt < 8; nt++) {
                int c0 = nt * 8 + 2 * (lane & 3);
                if (c0     > r0l)     s[nt][0] = -1e30f;
                if (c0 + 1 > r0l)     s[nt][1] = -1e30f;
                if (c0     > r0l + 8) s[nt][2] = -1e30f;
                if (c0 + 1 > r0l + 8) s[nt][3] = -1e30f;
            }
        }

        // ---- register online softmax (rows lr and lr+8) ----
        float tm0 = -1e30f, tm1 = -1e30f;
#pragma unroll
        for (int nt = 0; nt < 8; nt++) {
            tm0 = fmaxf(tm0, fmaxf(s[nt][0], s[nt][1]));
            tm1 = fmaxf(tm1, fmaxf(s[nt][2], s[nt][3]));
        }
        tm0 = fmaxf(tm0, __shfl_xor_sync(0xffffffffu, tm0, 1));
        tm0 = fmaxf(tm0, __shfl_xor_sync(0xffffffffu, tm0, 2));
        tm1 = fmaxf(tm1, __shfl_xor_sync(0xffffffffu, tm1, 1));
        tm1 = fmaxf(tm1, __shfl_xor_sync(0xffffffffu, tm1, 2));
        float nm0 = fmaxf(m0r, tm0), nm1 = fmaxf(m1r, tm1);
        float cor0 = __expf(m0r - nm0), cor1 = __expf(m1r - nm1);
        m0r = nm0; m1r = nm1;

        float sum0 = 0.f, sum1 = 0.f;
#pragma unroll
        for (int nt = 0; nt < 8; nt++) {
            s[nt][0] = __expf(s[nt][0] - nm0);
            s[nt][1] = __expf(s[nt][1] - nm0);
            s[nt][2] = __expf(s[nt][2] - nm1);
            s[nt][3] = __expf(s[nt][3] - nm1);
            sum0 += s[nt][0] + s[nt][1];
            sum1 += s[nt][2] + s[nt][3];
        }
        sum0 += __shfl_xor_sync(0xffffffffu, sum0, 1);
        sum0 += __shfl_xor_sync(0xffffffffu, sum0, 2);
        sum1 += __shfl_xor_sync(0xffffffffu, sum1, 1);
        sum1 += __shfl_xor_sync(0xffffffffu, sum1, 2);
        l0 = l0 * cor0 + sum0;
        l1 = l1 * cor1 + sum1;

#pragma unroll
        for (int nt = 0; nt < 16; nt++) {
            o[nt][0] *= cor0; o[nt][1] *= cor0;
            o[nt][2] *= cor1; o[nt][3] *= cor1;
        }

        // ---- O += P @ V : P frags built in-register from S frags ----
#pragma unroll
        for (int kk = 0; kk < 4; kk++) {
            uint32_t ah[4], al[4];
            {
                float v0 = s[2 * kk][0],     v1 = s[2 * kk][1];
                float v2 = s[2 * kk][2],     v3 = s[2 * kk][3];
                float w0 = s[2 * kk + 1][0], w1 = s[2 * kk + 1][1];
                float w2 = s[2 * kk + 1][2], w3 = s[2 * kk + 1][3];
                ah[0] = pack_bf2(v0, v1); ah[1] = pack_bf2(v2, v3);
                ah[2] = pack_bf2(w0, w1); ah[3] = pack_bf2(w2, w3);
                al[0] = pack_bf2(v0 - __uint_as_float(ah[0] << 16),
                                 v1 - __uint_as_float(ah[0] & 0xFFFF0000u));
                al[1] = pack_bf2(v2 - __uint_as_float(ah[1] << 16),
                                 v3 - __uint_as_float(ah[1] & 0xFFFF0000u));
                al[2] = pack_bf2(w0 - __uint_as_float(ah[2] << 16),
                                 w1 - __uint_as_float(ah[2] & 0xFFFF0000u));
                al[3] = pack_bf2(w2 - __uint_as_float(ah[3] << 16),
                                 w3 - __uint_as_float(ah[3] & 0xFFFF0000u));
            }
#pragma unroll
            for (int nb = 0; nb < 8; nb++) {
                uint32_t vh4[4], vl4[4];
                uint32_t vaddr = smb + A_VH + (kk * 16 + l8 * 8 + rin) * AQLD
                               + (nb * 16 + l16 * 8) * 2;
                LDM_X4T(vh4, vaddr);
                LDM_X4T(vl4, vaddr + ATILE);
#pragma unroll
                for (int hf = 0; hf < 2; hf++) {
                    mma_bf16(o[nb * 2 + hf], ah, &vh4[hf * 2]);
                    mma_bf16(o[nb * 2 + hf], ah, &vl4[hf * 2]);
                    mma_bf16(o[nb * 2 + hf], al, &vh4[hf * 2]);
                }
            }
        }
    }

    // ---- epilogue: normalize + bf16-split store for the O-projection ----
    float inv0 = 1.f / l0, inv1 = 1.f / l1;
    const size_t r0 = bbase + q0 + wid * 16 + (lane >> 2);
    const int gc = h * HD + 2 * (lane & 3);
#pragma unroll
    for (int nt = 0; nt < 16; nt++) {
        int col = gc + nt * 8;
        float v0 = o[nt][0] * inv0, v1 = o[nt][1] * inv0;
        uint32_t hh = pack_bf2(v0, v1);
        uint32_t ll = pack_bf2(v0 - __uint_as_float(hh << 16),
                               v1 - __uint_as_float(hh & 0xFFFF0000u));
        *(uint32_t*)(g_attnb_hi + r0 * HIDD + col) = hh;
        *(uint32_t*)(g_attnb_lo + r0 * HIDD + col) = ll;
        float v2 = o[nt][2] * inv1, v3 = o[nt][3] * inv1;
        hh = pack_bf2(v2, v3);
        ll = pack_bf2(v2 - __uint_as_float(hh << 16),
                      v3 - __uint_as_float(hh & 0xFFFF0000u));
        *(uint32_t*)(g_attnb_hi + (r0 + 8) * HIDD + col) = hh;
        *(uint32_t*)(g_attnb_lo + (r0 + 8) * HIDD + col) = ll;
    }
}

// ---------------------------------------------------------------------------
extern "C" void kernel_launch(void* const* d_in, const int* in_sizes, int n_in,
                              void* d_out, int out_size)
{
    const float* hidden = (const float*)d_in[0];
    const float* fcos   = (const float*)d_in[1];
    const float* fsin   = (const float*)d_in[2];
    const float* w_qkv  = (const float*)d_in[6];
    const float* w_o    = (const float*)d_in[7];
    float* out = (float*)d_out;

    float* qkv_f;
    __nv_bfloat16 *hid_hi, *hid_lo, *wqkv_hi, *wqkv_lo, *wo_hi, *wo_lo;
    __nv_bfloat16 *attn_hi, *attn_lo;
    cudaGetSymbolAddress((void**)&qkv_f,   g_qkv);
    cudaGetSymbolAddress((void**)&hid_hi,  g_hid_hi);
    cudaGetSymbolAddress((void**)&hid_lo,  g_hid_lo);
    cudaGetSymbolAddress((void**)&wqkv_hi, g_wqkv_hi);
    cudaGetSymbolAddress((void**)&wqkv_lo, g_wqkv_lo);
    cudaGetSymbolAddress((void**)&wo_hi,   g_wo_hi);
    cudaGetSymbolAddress((void**)&wo_lo,   g_wo_lo);
    cudaGetSymbolAddress((void**)&attn_hi, g_attnb_hi);
    cudaGetSymbolAddress((void**)&attn_lo, g_attnb_lo);

    cudaFuncSetAttribute(gemm_pre_kernel,
                         cudaFuncAttributeMaxDynamicSharedMemorySize, GQ_SMEM);
    cudaFuncSetAttribute(attn_kernel,
                         cudaFuncAttributeMaxDynamicSharedMemorySize, ATT_SMEM);

    const int M = BB * TT;  // 4096

    // 0) split fp32 operands into bf16 hi/lo
    split_kernel<<<8192, 256>>>(hidden, hid_hi, hid_lo, (BB * TT * HIDD) / 4);
    split_kernel<<<8192, 256>>>(w_qkv, wqkv_hi, wqkv_lo, (QKVW * HIDD) / 4);
    split_kernel<<<4096, 256>>>(w_o, wo_hi, wo_lo, (HIDD * HIDD) / 4);

    // 1) QKV projection -> g_qkv fp32
    gemm_pre_kernel<<<dim3(QKVW / 128, M / 256), 256, GQ_SMEM>>>(
        hid_hi, hid_lo, wqkv_hi, wqkv_lo, qkv_f, M, QKVW, HIDD);

    // 2) RoPE + scale-fold + bf16 split -> g_qkvb
    ropesplit_kernel<<<dim3(BB * TT, 8), 128>>>(fcos, fsin);

    // 3) causal GQA attention (tensor cores) -> g_attnb bf16 hi/lo
    attn_kernel<<<dim3(TT / 64, NH, BB), 128, ATT_SMEM>>>();

    // 4) output projection -> d_out fp32
    gemm_pre_kernel<<<dim3(HIDD / 128, M / 256), 256, GQ_SMEM>>>(
        attn_hi, attn_lo, wo_hi, wo_lo, out, M, HIDD, HIDD);
}